// round 1
// baseline (speedup 1.0000x reference)
#include <cuda_runtime.h>
#include <cstdint>
#include <cstddef>

#define NEXP 8
#define HDIM 1024
#define FDIM 4096

// intermediate activations: [E, T, F] fp32 = 256MB static device scratch
__device__ float g_inter[(size_t)NEXP * 2048 * FDIM];

__device__ __forceinline__ unsigned f2tf(float x) {
    unsigned u;
    asm("cvt.rna.tf32.f32 %0, %1;" : "=r"(u) : "f"(x));
    return u;
}

__device__ __forceinline__ void mma_tf32(float* c,
                                         unsigned a0, unsigned a1, unsigned a2, unsigned a3,
                                         unsigned b0, unsigned b1) {
    asm volatile(
        "mma.sync.aligned.m16n8k8.row.col.f32.tf32.tf32.f32 "
        "{%0,%1,%2,%3}, {%4,%5,%6,%7}, {%8,%9}, {%0,%1,%2,%3};"
        : "+f"(c[0]), "+f"(c[1]), "+f"(c[2]), "+f"(c[3])
        : "r"(a0), "r"(a1), "r"(a2), "r"(a3), "r"(b0), "r"(b1));
}

__device__ __forceinline__ float gelu_tanh(float x) {
    float x3 = x * x * x;
    return 0.5f * x * (1.0f + tanhf(0.7978845608028654f * (x + 0.044715f * x3)));
}

// C[M,N] = A[M,K] @ B[K,N] per expert (blockIdx.z), optional fused tanh-GELU.
// A row-major, B row-major. All dims multiples of 128 (K multiple of 16).
template <bool GELU>
__global__ __launch_bounds__(256)
void gemm_tf32_kernel(const float* __restrict__ Aall, const float* __restrict__ Ball,
                      float* __restrict__ Call, int M, int N, int K) {
    constexpr int BM = 128, BN = 128, BK = 16, LDB = 136;

    __shared__ unsigned As[2][BM * BK];   // XOR-swizzled, rows of 16 words
    __shared__ unsigned Bs[2][BK * LDB];  // row-major [k][n], padded to 136

    const int e = blockIdx.z;
    const float* A = Aall + (size_t)e * M * K;
    const float* B = Ball + (size_t)e * K * N;
    float* C = Call + (size_t)e * M * N;

    const int tid  = threadIdx.x;
    const int lane = tid & 31;
    const int wid  = tid >> 5;
    const int warp_m = wid & 1;   // 2 warps along M (64 rows each)
    const int warp_n = wid >> 1;  // 4 warps along N (32 cols each)
    const int mBase = blockIdx.y * BM;
    const int nBase = blockIdx.x * BN;

    float acc[4][4][4];
#pragma unroll
    for (int i = 0; i < 4; i++)
#pragma unroll
        for (int j = 0; j < 4; j++)
#pragma unroll
            for (int k = 0; k < 4; k++) acc[i][j][k] = 0.0f;

    // ---- global load coordinates ----
    const int aRow = tid >> 2;           // 0..63 (+64 for second half)
    const int aC4  = (tid & 3) << 2;     // 0,4,8,12
    const int bKr  = tid >> 5;           // 0..7 (+8 for second half)
    const int bNc  = (tid & 31) << 2;    // 0..124

    const float* Ap0 = A + (size_t)(mBase + aRow) * K + aC4;
    const float* Ap1 = A + (size_t)(mBase + aRow + 64) * K + aC4;
    const float* Bp0 = B + (size_t)bKr * N + nBase + bNc;
    const float* Bp1 = B + (size_t)(bKr + 8) * N + nBase + bNc;

    // swizzled A store word offsets: phys(m,k) = m*16 + ((k>>2 ^ ((m>>1)&3))<<2) + (k&3)
    const int aSw0 = aRow * 16 + (((aC4 >> 2) ^ ((aRow >> 1) & 3)) << 2);
    const int aSw1 = aSw0 + 64 * 16;  // ((m+64)>>1)&3 == (m>>1)&3
    const int bOff0 = bKr * LDB + bNc;
    const int bOff1 = (bKr + 8) * LDB + bNc;

    // fragment LDS coordinates
    const int q = lane >> 2;          // 0..7
    const int r = lane & 3;           // 0..3
    const int sA = (q >> 1) & 3;      // A swizzle selector (m0 multiple of 16 ⇒ s depends on q only)
    const int mW = warp_m * 64;
    const int nW = warp_n * 32;

    const int ntile = K / BK;

    float4 aR0, aR1, bR0, bR1;

    // ---- prologue: tile 0 ----
    aR0 = *(const float4*)Ap0;
    aR1 = *(const float4*)Ap1;
    bR0 = *(const float4*)Bp0;
    bR1 = *(const float4*)Bp1;
    {
        unsigned* as = As[0];
        unsigned* bs = Bs[0];
        *(uint4*)(as + aSw0) = make_uint4(f2tf(aR0.x), f2tf(aR0.y), f2tf(aR0.z), f2tf(aR0.w));
        *(uint4*)(as + aSw1) = make_uint4(f2tf(aR1.x), f2tf(aR1.y), f2tf(aR1.z), f2tf(aR1.w));
        *(uint4*)(bs + bOff0) = make_uint4(f2tf(bR0.x), f2tf(bR0.y), f2tf(bR0.z), f2tf(bR0.w));
        *(uint4*)(bs + bOff1) = make_uint4(f2tf(bR1.x), f2tf(bR1.y), f2tf(bR1.z), f2tf(bR1.w));
    }
    __syncthreads();

    for (int t = 0; t < ntile; ++t) {
        // prefetch next tile into registers (overlaps with compute)
        if (t + 1 < ntile) {
            aR0 = *(const float4*)(Ap0 + (size_t)(t + 1) * BK);
            aR1 = *(const float4*)(Ap1 + (size_t)(t + 1) * BK);
            bR0 = *(const float4*)(Bp0 + (size_t)(t + 1) * BK * N);
            bR1 = *(const float4*)(Bp1 + (size_t)(t + 1) * BK * N);
        }

        // ---- compute on buffer t&1 ----
        const unsigned* as = As[t & 1];
        const unsigned* bs = Bs[t & 1];
#pragma unroll
        for (int ks = 0; ks < 2; ++ks) {
            unsigned af[4][4];
#pragma unroll
            for (int mt = 0; mt < 4; ++mt) {
                const int m0 = mW + mt * 16 + q;
                const int base = m0 * 16 + r;
                const int cLo = ((2 * ks) ^ sA) << 2;
                const int cHi = ((2 * ks + 1) ^ sA) << 2;
                af[mt][0] = as[base + cLo];
                af[mt][1] = as[base + 128 + cLo];
                af[mt][2] = as[base + cHi];
                af[mt][3] = as[base + 128 + cHi];
            }
            unsigned bf[4][2];
#pragma unroll
            for (int nt = 0; nt < 4; ++nt) {
                const int n0 = nW + nt * 8 + q;
                bf[nt][0] = bs[(ks * 8 + r) * LDB + n0];
                bf[nt][1] = bs[(ks * 8 + 4 + r) * LDB + n0];
            }
#pragma unroll
            for (int mt = 0; mt < 4; ++mt)
#pragma unroll
                for (int nt = 0; nt < 4; ++nt)
                    mma_tf32(acc[mt][nt], af[mt][0], af[mt][1], af[mt][2], af[mt][3],
                             bf[nt][0], bf[nt][1]);
        }

        // ---- stage next tile into the other buffer ----
        if (t + 1 < ntile) {
            unsigned* asw = As[(t + 1) & 1];
            unsigned* bsw = Bs[(t + 1) & 1];
            *(uint4*)(asw + aSw0) = make_uint4(f2tf(aR0.x), f2tf(aR0.y), f2tf(aR0.z), f2tf(aR0.w));
            *(uint4*)(asw + aSw1) = make_uint4(f2tf(aR1.x), f2tf(aR1.y), f2tf(aR1.z), f2tf(aR1.w));
            *(uint4*)(bsw + bOff0) = make_uint4(f2tf(bR0.x), f2tf(bR0.y), f2tf(bR0.z), f2tf(bR0.w));
            *(uint4*)(bsw + bOff1) = make_uint4(f2tf(bR1.x), f2tf(bR1.y), f2tf(bR1.z), f2tf(bR1.w));
            __syncthreads();
        }
    }

    // ---- epilogue ----
#pragma unroll
    for (int mt = 0; mt < 4; ++mt) {
        const int row = mBase + mW + mt * 16 + q;
#pragma unroll
        for (int nt = 0; nt < 4; ++nt) {
            const int col = nBase + nW + nt * 8 + 2 * r;
            float2 v0 = make_float2(acc[mt][nt][0], acc[mt][nt][1]);
            float2 v1 = make_float2(acc[mt][nt][2], acc[mt][nt][3]);
            if (GELU) {
                v0.x = gelu_tanh(v0.x); v0.y = gelu_tanh(v0.y);
                v1.x = gelu_tanh(v1.x); v1.y = gelu_tanh(v1.y);
            }
            *(float2*)(C + (size_t)row * N + col) = v0;
            *(float2*)(C + (size_t)(row + 8) * N + col) = v1;
        }
    }
}

extern "C" void kernel_launch(void* const* d_in, const int* in_sizes, int n_in,
                              void* d_out, int out_size) {
    const float* x  = (const float*)d_in[0];
    const float* w1 = (const float*)d_in[1];
    const float* w2 = (const float*)d_in[2];
    float* out = (float*)d_out;

    float* inter = nullptr;
    cudaGetSymbolAddress((void**)&inter, g_inter);

    const int Mtot = in_sizes[0] / HDIM;   // total tokens (16384)
    const int T = Mtot / NEXP;             // tokens per expert (2048)

    dim3 blk(256);
    // GEMM1 + GELU: [T,H] @ [H,F] -> inter [T,F] per expert
    dim3 g1(FDIM / 128, T / 128, NEXP);
    gemm_tf32_kernel<true><<<g1, blk>>>(x, w1, inter, T, FDIM, HDIM);
    // GEMM2: inter [T,F] @ [F,H] -> out [T,H] per expert
    dim3 g2(HDIM / 128, T / 128, NEXP);
    gemm_tf32_kernel<false><<<g2, blk>>>(inter, w2, out, T, HDIM, FDIM);
}

// round 2
// speedup vs baseline: 1.5807x; 1.5807x over previous
#include <cuda_runtime.h>
#include <cstdint>
#include <cstddef>

#define NEXP 8
#define HDIM 1024
#define FDIM 4096

// intermediate activations: [E, T, F] fp32 = 256MB static device scratch
__device__ float g_inter[(size_t)NEXP * 2048 * FDIM];

__device__ __forceinline__ unsigned f2tf(float x) {
    unsigned u;
    asm("cvt.rna.tf32.f32 %0, %1;" : "=r"(u) : "f"(x));
    return u;
}

__device__ __forceinline__ void mma_tf32(float* c,
                                         unsigned a0, unsigned a1, unsigned a2, unsigned a3,
                                         unsigned b0, unsigned b1) {
    asm volatile(
        "mma.sync.aligned.m16n8k8.row.col.f32.tf32.tf32.f32 "
        "{%0,%1,%2,%3}, {%4,%5,%6,%7}, {%8,%9}, {%0,%1,%2,%3};"
        : "+f"(c[0]), "+f"(c[1]), "+f"(c[2]), "+f"(c[3])
        : "r"(a0), "r"(a1), "r"(a2), "r"(a3), "r"(b0), "r"(b1));
}

__device__ __forceinline__ float gelu_tanh(float x) {
    float x3 = x * x * x;
    return 0.5f * x * (1.0f + tanhf(0.7978845608028654f * (x + 0.044715f * x3)));
}

// C[M,N] = A[M,K] @ B[K,N] per expert (blockIdx.z), optional fused tanh-GELU.
// A row-major, B row-major. All dims multiples of 128 (K multiple of 16).
template <bool GELU>
__global__ __launch_bounds__(256)
void gemm_tf32_kernel(const float* __restrict__ Aall, const float* __restrict__ Ball,
                      float* __restrict__ Call, int M, int N, int K) {
    constexpr int BM = 128, BN = 128, BK = 16, LDB = 136;

    __shared__ unsigned As[2][BM * BK];   // XOR-swizzled, rows of 16 words
    __shared__ unsigned Bs[2][BK * LDB];  // row-major [k][n], padded to 136

    const int e = blockIdx.z;
    const float* A = Aall + (size_t)e * M * K;
    const float* B = Ball + (size_t)e * K * N;
    float* C = Call + (size_t)e * M * N;

    const int tid  = threadIdx.x;
    const int lane = tid & 31;
    const int wid  = tid >> 5;
    const int warp_m = wid & 1;   // 2 warps along M (64 rows each)
    const int warp_n = wid >> 1;  // 4 warps along N (32 cols each)
    const int mBase = blockIdx.y * BM;
    const int nBase = blockIdx.x * BN;

    float acc[4][4][4];
#pragma unroll
    for (int i = 0; i < 4; i++)
#pragma unroll
        for (int j = 0; j < 4; j++)
#pragma unroll
            for (int k = 0; k < 4; k++) acc[i][j][k] = 0.0f;

    // ---- global load coordinates ----
    const int aRow = tid >> 2;           // 0..63 (+64 for second half)
    const int aC4  = (tid & 3) << 2;     // 0,4,8,12
    const int bKr  = tid >> 5;           // 0..7 (+8 for second half)
    const int bNc  = (tid & 31) << 2;    // 0..124

    const float* Ap0 = A + (size_t)(mBase + aRow) * K + aC4;
    const float* Ap1 = A + (size_t)(mBase + aRow + 64) * K + aC4;
    const float* Bp0 = B + (size_t)bKr * N + nBase + bNc;
    const float* Bp1 = B + (size_t)(bKr + 8) * N + nBase + bNc;

    // swizzled A store word offsets: phys(m,k) = m*16 + ((k>>2 ^ ((m>>1)&3))<<2) + (k&3)
    const int aSw0 = aRow * 16 + (((aC4 >> 2) ^ ((aRow >> 1) & 3)) << 2);
    const int aSw1 = aSw0 + 64 * 16;  // ((m+64)>>1)&3 == (m>>1)&3
    const int bOff0 = bKr * LDB + bNc;
    const int bOff1 = (bKr + 8) * LDB + bNc;

    // fragment LDS coordinates
    const int q = lane >> 2;          // 0..7
    const int r = lane & 3;           // 0..3
    const int sA = (q >> 1) & 3;      // A swizzle selector (m0 multiple of 16 ⇒ s depends on q only)
    const int mW = warp_m * 64;
    const int nW = warp_n * 32;

    const int ntile = K / BK;

    float4 aR0, aR1, bR0, bR1;

    // ---- prologue: tile 0 ----
    aR0 = *(const float4*)Ap0;
    aR1 = *(const float4*)Ap1;
    bR0 = *(const float4*)Bp0;
    bR1 = *(const float4*)Bp1;
    {
        unsigned* as = As[0];
        unsigned* bs = Bs[0];
        *(uint4*)(as + aSw0) = make_uint4(f2tf(aR0.x), f2tf(aR0.y), f2tf(aR0.z), f2tf(aR0.w));
        *(uint4*)(as + aSw1) = make_uint4(f2tf(aR1.x), f2tf(aR1.y), f2tf(aR1.z), f2tf(aR1.w));
        *(uint4*)(bs + bOff0) = make_uint4(f2tf(bR0.x), f2tf(bR0.y), f2tf(bR0.z), f2tf(bR0.w));
        *(uint4*)(bs + bOff1) = make_uint4(f2tf(bR1.x), f2tf(bR1.y), f2tf(bR1.z), f2tf(bR1.w));
    }
    __syncthreads();

    for (int t = 0; t < ntile; ++t) {
        // prefetch next tile into registers (overlaps with compute)
        if (t + 1 < ntile) {
            aR0 = *(const float4*)(Ap0 + (size_t)(t + 1) * BK);
            aR1 = *(const float4*)(Ap1 + (size_t)(t + 1) * BK);
            bR0 = *(const float4*)(Bp0 + (size_t)(t + 1) * BK * N);
            bR1 = *(const float4*)(Bp1 + (size_t)(t + 1) * BK * N);
        }

        // ---- compute on buffer t&1 ----
        const unsigned* as = As[t & 1];
        const unsigned* bs = Bs[t & 1];
#pragma unroll
        for (int ks = 0; ks < 2; ++ks) {
            unsigned af[4][4];
#pragma unroll
            for (int mt = 0; mt < 4; ++mt) {
                const int m0 = mW + mt * 16 + q;
                const int base = m0 * 16 + r;
                const int cLo = ((2 * ks) ^ sA) << 2;
                const int cHi = ((2 * ks + 1) ^ sA) << 2;
                af[mt][0] = as[base + cLo];
                af[mt][1] = as[base + 128 + cLo];
                af[mt][2] = as[base + cHi];
                af[mt][3] = as[base + 128 + cHi];
            }
            unsigned bf[4][2];
#pragma unroll
            for (int nt = 0; nt < 4; ++nt) {
                const int n0 = nW + nt * 8 + q;
                bf[nt][0] = bs[(ks * 8 + r) * LDB + n0];
                bf[nt][1] = bs[(ks * 8 + 4 + r) * LDB + n0];
            }
#pragma unroll
            for (int mt = 0; mt < 4; ++mt)
#pragma unroll
                for (int nt = 0; nt < 4; ++nt)
                    mma_tf32(acc[mt][nt], af[mt][0], af[mt][1], af[mt][2], af[mt][3],
                             bf[nt][0], bf[nt][1]);
        }

        // ---- stage next tile into the other buffer ----
        if (t + 1 < ntile) {
            unsigned* asw = As[(t + 1) & 1];
            unsigned* bsw = Bs[(t + 1) & 1];
            *(uint4*)(asw + aSw0) = make_uint4(f2tf(aR0.x), f2tf(aR0.y), f2tf(aR0.z), f2tf(aR0.w));
            *(uint4*)(asw + aSw1) = make_uint4(f2tf(aR1.x), f2tf(aR1.y), f2tf(aR1.z), f2tf(aR1.w));
            *(uint4*)(bsw + bOff0) = make_uint4(f2tf(bR0.x), f2tf(bR0.y), f2tf(bR0.z), f2tf(bR0.w));
            *(uint4*)(bsw + bOff1) = make_uint4(f2tf(bR1.x), f2tf(bR1.y), f2tf(bR1.z), f2tf(bR1.w));
            __syncthreads();
        }
    }

    // ---- epilogue ----
#pragma unroll
    for (int mt = 0; mt < 4; ++mt) {
        const int row = mBase + mW + mt * 16 + q;
#pragma unroll
        for (int nt = 0; nt < 4; ++nt) {
            const int col = nBase + nW + nt * 8 + 2 * r;
            float2 v0 = make_float2(acc[mt][nt][0], acc[mt][nt][1]);
            float2 v1 = make_float2(acc[mt][nt][2], acc[mt][nt][3]);
            if (GELU) {
                v0.x = gelu_tanh(v0.x); v0.y = gelu_tanh(v0.y);
                v1.x = gelu_tanh(v1.x); v1.y = gelu_tanh(v1.y);
            }
            *(float2*)(C + (size_t)row * N + col) = v0;
            *(float2*)(C + (size_t)(row + 8) * N + col) = v1;
        }
    }
}

extern "C" void kernel_launch(void* const* d_in, const int* in_sizes, int n_in,
                              void* d_out, int out_size) {
    const float* x  = (const float*)d_in[0];
    const float* w1 = (const float*)d_in[1];
    const float* w2 = (const float*)d_in[2];
    float* out = (float*)d_out;

    float* inter = nullptr;
    cudaGetSymbolAddress((void**)&inter, g_inter);

    const int Mtot = in_sizes[0] / HDIM;   // total tokens (16384)
    const int T = Mtot / NEXP;             // tokens per expert (2048)

    dim3 blk(256);
    // GEMM1 + GELU: [T,H] @ [H,F] -> inter [T,F] per expert
    dim3 g1(FDIM / 128, T / 128, NEXP);
    gemm_tf32_kernel<true><<<g1, blk>>>(x, w1, inter, T, FDIM, HDIM);
    // GEMM2: inter [T,F] @ [F,H] -> out [T,H] per expert
    dim3 g2(HDIM / 128, T / 128, NEXP);
    gemm_tf32_kernel<false><<<g2, blk>>>(inter, w2, out, T, HDIM, FDIM);
}